// round 13
// baseline (speedup 1.0000x reference)
#include <cuda_runtime.h>
#include <cuda_bf16.h>
#include <cuda_fp16.h>
#include <cstdint>

#define BBq 4
#define CCq 256
#define NNq 4096
#define CTq 256

typedef __nv_bfloat16 bf16;
typedef __nv_bfloat162 bf162;

// ---------------- persistent planes (device globals) ----------------
__device__ __align__(256) bf16   g_xth[(size_t)BBq * NNq * CCq];
__device__ __align__(256) bf16   g_xtl[(size_t)BBq * NNq * CCq];
__device__ __align__(256) __half g_xtf[(size_t)BBq * NNq * CCq];
__device__ __align__(256) __half g_qf [(size_t)BBq * NNq * CTq];
__device__ __align__(256) __half g_kf [(size_t)BBq * NNq * CTq];
__device__ __align__(256) __half g_vf [(size_t)BBq * NNq * CTq];
__device__ __align__(256) __half g_cf [(size_t)BBq * NNq * CTq];
__device__ __align__(256) __half g_wqf[CTq * CCq];
__device__ __align__(256) __half g_wkf[CTq * CCq];
__device__ __align__(256) __half g_wvf[CTq * CCq];
__device__ __align__(256) __half g_wof[CCq * CTq];      // Wo cols [0,256) fp16
__device__ __align__(256) bf16   g_woh[CCq * CTq];      // Wo cols [256,512) hi
__device__ __align__(256) bf16   g_wol[CCq * CTq];      // Wo cols [256,512) lo

// ---------------- helpers ----------------
__device__ __forceinline__ uint32_t smem_u32(const void* p) {
    uint32_t a;
    asm("{ .reg .u64 t; cvta.to.shared.u64 t, %1; cvt.u32.u64 %0, t; }"
        : "=r"(a) : "l"(p));
    return a;
}
#define CP16(dst, src) \
    asm volatile("cp.async.cg.shared.global [%0], [%1], 16;" \
                 :: "r"(dst), "l"(src))
#define CP_COMMIT() asm volatile("cp.async.commit_group;" ::: "memory")

#define LDSM4(r0, r1, r2, r3, addr) \
    asm volatile("ldmatrix.sync.aligned.m8n8.x4.shared.b16 {%0,%1,%2,%3}, [%4];" \
                 : "=r"(r0), "=r"(r1), "=r"(r2), "=r"(r3) : "r"(addr))
#define LDSM4T(r0, r1, r2, r3, addr) \
    asm volatile("ldmatrix.sync.aligned.m8n8.x4.trans.shared.b16 {%0,%1,%2,%3}, [%4];" \
                 : "=r"(r0), "=r"(r1), "=r"(r2), "=r"(r3) : "r"(addr))

__device__ __forceinline__ void mma_bf16(float* d, const uint32_t* a,
                                         const uint32_t* b) {
    asm volatile(
        "mma.sync.aligned.m16n8k16.row.col.f32.bf16.bf16.f32 "
        "{%0,%1,%2,%3}, {%4,%5,%6,%7}, {%8,%9}, {%0,%1,%2,%3};"
        : "+f"(d[0]), "+f"(d[1]), "+f"(d[2]), "+f"(d[3])
        : "r"(a[0]), "r"(a[1]), "r"(a[2]), "r"(a[3]), "r"(b[0]), "r"(b[1]));
}
__device__ __forceinline__ void mma_f16(float* d, const uint32_t* a,
                                        uint32_t b0, uint32_t b1) {
    asm volatile(
        "mma.sync.aligned.m16n8k16.row.col.f32.f16.f16.f32 "
        "{%0,%1,%2,%3}, {%4,%5,%6,%7}, {%8,%9}, {%0,%1,%2,%3};"
        : "+f"(d[0]), "+f"(d[1]), "+f"(d[2]), "+f"(d[3])
        : "r"(a[0]), "r"(a[1]), "r"(a[2]), "r"(a[3]), "r"(b0), "r"(b1));
}
__device__ __forceinline__ uint32_t pack_h2(float a, float b) {
    __half2 h = __floats2half2_rn(a, b);
    return *reinterpret_cast<uint32_t*>(&h);
}
__device__ __forceinline__ uint32_t ex2_h2(uint32_t x) {
    uint32_t r;
    asm("ex2.approx.f16x2 %0, %1;" : "=r"(r) : "r"(x));
    return r;
}

// ---------------- fused qkv: A resident in smem, loop over 3 weights -------
// grid (32, 2, BBq). smem: A 64KB (8 panels x 8KB) + B ring 4 x 8KB = 96KB.
// For each w: 8 k-chunks; B chunk = 128 cols x 32 k fp16 = 8KB.
#define QA_BYTES 65536
#define QB_STG 8192
#define QSMEM (QA_BYTES + 4 * QB_STG)

__global__ __launch_bounds__(256, 1) void qkv_fused(
    const __half* __restrict__ xtf,
    const __half* __restrict__ Wq, const __half* __restrict__ Wk,
    const __half* __restrict__ Wv,
    __half* __restrict__ qf, __half* __restrict__ kf, __half* __restrict__ vf)
{
    extern __shared__ char sm[];
    const uint32_t smb = smem_u32(sm);
    const uint32_t Bs = smb + QA_BYTES;
    const int tid = threadIdx.x;
    const int wid = tid >> 5, lane = tid & 31;
    const int b = blockIdx.z;
    const int row0 = blockIdx.x * 128;
    const int col0 = blockIdx.y * 128;

    const __half* __restrict__ Ab =
        xtf + (long long)b * NNq * CCq + (long long)row0 * CCq;
    const __half* Wlist[3] = {Wq + (size_t)col0 * CCq, Wk + (size_t)col0 * CCq,
                              Wv + (size_t)col0 * CCq};
    __half* Dlist[3] = {qf + (long long)b * NNq * CTq,
                        kf + (long long)b * NNq * CTq,
                        vf + (long long)b * NNq * CTq};

    // ---- stage A once: 128 rows x 256 ct, 8 swizzled panels of 32 ct ----
#pragma unroll
    for (int i = 0; i < 16; i++) {
        int idx = tid + i * 256;
        int row = idx >> 5, cc = idx & 31;
        uint32_t dst = smb + (cc >> 2) * 8192 + row * 64 +
                       (uint32_t)(((cc & 3) ^ ((row >> 1) & 3)) << 4);
        CP16(dst, Ab + (size_t)row * CCq + cc * 8);
    }
    CP_COMMIT();

    // B staging indices: 2 x 16B per thread (8KB per chunk)
    int br_[2], bc_[2];
    uint32_t bdst[2];
#pragma unroll
    for (int i = 0; i < 2; i++) {
        int idx = tid + i * 256;
        br_[i] = idx >> 1;               // 0..127 (col)
        bc_[i] = idx & 1;                // 0..1 (16B chunk within 32k = 64B)
        // row stride 64B; swizzle on 4 chunks of row pair pattern (row*64, 2 chunks)
        bdst[i] = br_[i] * 64 + ((uint32_t)((bc_[i] ^ ((br_[i] >> 1) & 1)) << 4));
    }
    // NOTE: B rows are 64B (32 k fp16). ldmatrix phase needs conflict-free
    // across 16 rows x 2 chunks; use xor with bit0 of (row>>1).

    const int lr = lane & 15, lh = lane >> 4;
    // A fragment offsets (panel-relative), ksl in {0,1}
    uint32_t aoff[4][2];
#pragma unroll
    for (int mf = 0; mf < 4; mf++)
#pragma unroll
        for (int ksl = 0; ksl < 2; ksl++) {
            int R = (wid & 1) * 64 + mf * 16 + lr;
            int ch = ksl * 2 + lh;
            aoff[mf][ksl] = R * 64 + ((ch ^ ((R >> 1) & 3)) << 4);
        }
    // B fragment offsets: rows = cols of W tile (128), 64B rows, 4 x 16B per 2 rows
    // ldmatrix loads 16 rows x 16 bytes: addr per (lane row lr + 16*lh grouping)
    uint32_t boff[2][2];
#pragma unroll
    for (int p = 0; p < 2; p++)
#pragma unroll
        for (int ksl = 0; ksl < 2; ksl++) {
            int R = (wid >> 1) * 32 + p * 16 + lr;      // col row in tile
            int ch = ksl * 2 + lh;                      // 4 x 16B chunks per row
            // row is 64B = 4 chunks; swizzle: ch ^ ((R>>1)&3) keeps 4-bank spread
            boff[p][ksl] = R * 64 + ((ch ^ ((R >> 1) & 3)) << 4);
        }
    // B staging must match: dst = col*64 + ((chunk ^ ((col>>1)&3))<<4), chunk 0..3
    // Rebuild bdst accordingly (4 chunks per col row of 64B):
#pragma unroll
    for (int i = 0; i < 2; i++) {
        int idx = tid + i * 256;
        int col = idx >> 2;              // 0..127
        int ck = idx & 3;                // 0..3
        br_[i] = col; bc_[i] = ck;
        bdst[i] = col * 64 + ((uint32_t)((ck ^ ((col >> 1) & 3)) << 4));
    }

    auto stageB = [&](int t) {  // t = w*8 + c
        const int w = t >> 3, c = t & 7;
        const __half* Wb = Wlist[w];
        const uint32_t sb = Bs + (uint32_t)(t & 3) * QB_STG;
#pragma unroll
        for (int i = 0; i < 2; i++)
            CP16(sb + bdst[i], Wb + (size_t)br_[i] * CCq + c * 32 + bc_[i] * 8);
        CP_COMMIT();
    };
    stageB(0); stageB(1); stageB(2);

    const int g = lane >> 2, t2 = (lane & 3) * 2;

    for (int w = 0; w < 3; w++) {
        float acc[4][4][4];
#pragma unroll
        for (int mf = 0; mf < 4; mf++)
#pragma unroll
            for (int nf = 0; nf < 4; nf++)
#pragma unroll
                for (int r = 0; r < 4; r++) acc[mf][nf][r] = 0.f;

        for (int c = 0; c < 8; c++) {
            const int t = w * 8 + c;
            asm volatile("cp.async.wait_group 2;" ::: "memory");
            __syncthreads();
            const uint32_t sb = Bs + (uint32_t)(t & 3) * QB_STG;
#pragma unroll
            for (int ksl = 0; ksl < 2; ksl++) {
                uint32_t ah[4][4], bh[4][2];
#pragma unroll
                for (int mf = 0; mf < 4; mf++)
                    LDSM4(ah[mf][0], ah[mf][1], ah[mf][2], ah[mf][3],
                          smb + c * 8192 + aoff[mf][ksl]);
#pragma unroll
                for (int p = 0; p < 2; p++) {
                    uint32_t q0, q1, q2, q3;
                    LDSM4(q0, q1, q2, q3, sb + boff[p][ksl]);
                    bh[2 * p][0] = q0; bh[2 * p][1] = q2;
                    bh[2 * p + 1][0] = q1; bh[2 * p + 1][1] = q3;
                }
#pragma unroll
                for (int mf = 0; mf < 4; mf++)
#pragma unroll
                    for (int nf = 0; nf < 4; nf++)
                        mma_f16(acc[mf][nf], ah[mf], bh[nf][0], bh[nf][1]);
            }
            if (t + 3 < 24) stageB(t + 3);
            else CP_COMMIT();
        }

        const float scale = (w == 0) ? 0.0625f * 1.44269504089f : 1.0f;
        __half* __restrict__ Db = Dlist[w];
#pragma unroll
        for (int mf = 0; mf < 4; mf++) {
            const int gm = row0 + (wid & 1) * 64 + mf * 16 + g;
#pragma unroll
            for (int nf = 0; nf < 4; nf++) {
                const int gn = col0 + (wid >> 1) * 32 + nf * 8 + t2;
                __half2 a01 = __floats2half2_rn(acc[mf][nf][0] * scale,
                                                acc[mf][nf][1] * scale);
                __half2 a23 = __floats2half2_rn(acc[mf][nf][2] * scale,
                                                acc[mf][nf][3] * scale);
                *reinterpret_cast<__half2*>(&Db[(size_t)gm * CTq + gn]) = a01;
                *reinterpret_cast<__half2*>(&Db[(size_t)(gm + 8) * CTq + gn]) = a23;
            }
        }
    }
}

// ---------------- out projection: split precision (unchanged) -------------
#define OSTG 32768
#define OSMEM (4 * OSTG)

__global__ __launch_bounds__(256, 1) void gemm_out(
    const __half* __restrict__ cf,
    const bf16* __restrict__ xth, const bf16* __restrict__ xtl,
    const __half* __restrict__ wof,
    const bf16* __restrict__ woh, const bf16* __restrict__ wol,
    float* __restrict__ Df)
{
    extern __shared__ char sm[];
    const uint32_t smb = smem_u32(sm);
    const int tid = threadIdx.x;
    const int wid = tid >> 5, lane = tid & 31;
    const int row0 = blockIdx.x * 128;
    const int col0 = blockIdx.y * 128;
    const int b = blockIdx.z;

    const __half* __restrict__ Afb = cf + (long long)b * NNq * CTq +
                                     (long long)row0 * CTq;
    const bf16* __restrict__ Ahb = xth + (long long)b * NNq * CCq +
                                   (long long)row0 * CCq;
    const bf16* __restrict__ Alb = xtl + (long long)b * NNq * CCq +
                                   (long long)row0 * CCq;
    const __half* __restrict__ Bfb = wof + (size_t)col0 * CTq;
    const bf16* __restrict__ Bhb = woh + (size_t)col0 * CTq;
    const bf16* __restrict__ Blb = wol + (size_t)col0 * CTq;

    int sr[2], sc[2];
    uint32_t sdst[2];
#pragma unroll
    for (int i = 0; i < 2; i++) {
        int idx = tid + i * 256;
        sr[i] = idx >> 2;
        sc[i] = idx & 3;
        sdst[i] = sr[i] * 64 + ((sc[i] ^ ((sr[i] >> 1) & 3)) << 4);
    }
    const int lr = lane & 15, lh = lane >> 4;
    uint32_t aoff[4][2], boff[2][2];
#pragma unroll
    for (int mf = 0; mf < 4; mf++)
#pragma unroll
        for (int ks = 0; ks < 2; ks++) {
            int R = (wid & 1) * 64 + mf * 16 + lr;
            int ch = ks * 2 + lh;
            aoff[mf][ks] = R * 64 + ((ch ^ ((R >> 1) & 3)) << 4);
        }
#pragma unroll
    for (int p = 0; p < 2; p++)
#pragma unroll
        for (int ks = 0; ks < 2; ks++) {
            int R = (wid >> 1) * 32 + p * 16 + lr;
            int ch = ks * 2 + lh;
            boff[p][ks] = R * 64 + ((ch ^ ((R >> 1) & 3)) << 4);
        }

    float acc[4][4][4];
#pragma unroll
    for (int mf = 0; mf < 4; mf++)
#pragma unroll
        for (int nf = 0; nf < 4; nf++)
#pragma unroll
            for (int r = 0; r < 4; r++) acc[mf][nf][r] = 0.f;

    auto stageg = [&](int gc) {
        const uint32_t sb = smb + (uint32_t)(gc & 3) * OSTG;
        if (gc < 8) {
            const int kc = gc * 32;
#pragma unroll
            for (int i = 0; i < 2; i++) {
                CP16(sb + sdst[i],        Afb + (size_t)sr[i] * CTq + kc + sc[i] * 8);
                CP16(sb + 8192 + sdst[i], Bfb + (size_t)sr[i] * CTq + kc + sc[i] * 8);
            }
        } else {
            const int kc = (gc - 8) * 32;
#pragma unroll
            for (int i = 0; i < 2; i++) {
                const uint32_t d = sdst[i];
                CP16(sb + d,         Ahb + (size_t)sr[i] * CCq + kc + sc[i] * 8);
                CP16(sb + 8192 + d,  Alb + (size_t)sr[i] * CCq + kc + sc[i] * 8);
                CP16(sb + 16384 + d, Bhb + (size_t)sr[i] * CTq + kc + sc[i] * 8);
                CP16(sb + 24576 + d, Blb + (size_t)sr[i] * CTq + kc + sc[i] * 8);
            }
        }
        CP_COMMIT();
    };

    stageg(0); stageg(1); stageg(2);

    for (int gc = 0; gc < 16; gc++) {
        asm volatile("cp.async.wait_group 2;" ::: "memory");
        __syncthreads();
        const uint32_t sb = smb + (uint32_t)(gc & 3) * OSTG;
        if (gc < 8) {
#pragma unroll
            for (int ks = 0; ks < 2; ks++) {
                uint32_t ah[4][4], bh[4][2];
#pragma unroll
                for (int mf = 0; mf < 4; mf++)
                    LDSM4(ah[mf][0], ah[mf][1], ah[mf][2], ah[mf][3],
                          sb + aoff[mf][ks]);
#pragma unroll
                for (int p = 0; p < 2; p++) {
                    uint32_t t0, t1, t2, t3;
                    LDSM4(t0, t1, t2, t3, sb + 8192 + boff[p][ks]);
                    bh[2 * p][0] = t0; bh[2 * p][1] = t2;
                    bh[2 * p + 1][0] = t1; bh[2 * p + 1][1] = t3;
                }
#pragma unroll
                for (int mf = 0; mf < 4; mf++)
#pragma unroll
                    for (int nf = 0; nf < 4; nf++)
                        mma_f16(acc[mf][nf], ah[mf], bh[nf][0], bh[nf][1]);
            }
        } else {
#pragma unroll
            for (int ks = 0; ks < 2; ks++) {
                uint32_t ah[4][4], al[4][4], bh[4][2], bl[4][2];
#pragma unroll
                for (int mf = 0; mf < 4; mf++) {
                    LDSM4(ah[mf][0], ah[mf][1], ah[mf][2], ah[mf][3],
                          sb + aoff[mf][ks]);
                    LDSM4(al[mf][0], al[mf][1], al[mf][2], al[mf][3],
                          sb + 8192 + aoff[mf][ks]);
                }
#pragma unroll
                for (int p = 0; p < 2; p++) {
                    uint32_t t0, t1, t2, t3;
                    LDSM4(t0, t1, t2, t3, sb + 16384 + boff[p][ks]);
                    bh[2 * p][0] = t0; bh[2 * p][1] = t2;
                    bh[2 * p + 1][0] = t1; bh[2 * p + 1][1] = t3;
                    LDSM4(t0, t1, t2, t3, sb + 24576 + boff[p][ks]);
                    bl[2 * p][0] = t0; bl[2 * p][1] = t2;
                    bl[2 * p + 1][0] = t1; bl[2 * p + 1][1] = t3;
                }
#pragma unroll
                for (int mf = 0; mf < 4; mf++)
#pragma unroll
                    for (int nf = 0; nf < 4; nf++) {
                        mma_bf16(acc[mf][nf], ah[mf], bh[nf]);
                        mma_bf16(acc[mf][nf], ah[mf], bl[nf]);
                        mma_bf16(acc[mf][nf], al[mf], bh[nf]);
                    }
            }
        }
        if (gc + 3 < 16) stageg(gc + 3);
        else CP_COMMIT();
    }

    const int g = lane >> 2, t2 = (lane & 3) * 2;
    float* __restrict__ Dfb = Df + (long long)b * CCq * NNq;
#pragma unroll
    for (int mf = 0; mf < 4; mf++) {
        const int gm = row0 + (wid & 1) * 64 + mf * 16 + g;
#pragma unroll
        for (int nf = 0; nf < 4; nf++) {
            const int gn = col0 + (wid >> 1) * 32 + nf * 8 + t2;
            Dfb[(size_t)gn * NNq + gm] = acc[mf][nf][0];
            Dfb[(size_t)(gn + 1) * NNq + gm] = acc[mf][nf][1];
            Dfb[(size_t)gn * NNq + gm + 8] = acc[mf][nf][2];
            Dfb[(size_t)(gn + 1) * NNq + gm + 8] = acc[mf][nf][3];
        }
    }
}

// ---------------- fused attention: 6-buffer ring (unchanged from R12) ------
#define FM_SMEM 196608

__global__ __launch_bounds__(256, 1) void fmha(
    const __half* __restrict__ qf, const __half* __restrict__ kf,
    const __half* __restrict__ vf, __half* __restrict__ cfp)
{
    extern __shared__ char sm[];
    const uint32_t smb = smem_u32(sm);
    const int tid = threadIdx.x, wid = tid >> 5, lane = tid & 31;
    const int b = blockIdx.z, row0 = blockIdx.x * 128;
    const long long sQ = (long long)NNq * CTq;
    const __half* __restrict__ qb = qf + b * sQ + (long long)row0 * CTq;
    const __half* __restrict__ kb = kf + b * sQ;
    const __half* __restrict__ vb = vf + b * sQ;

#pragma unroll
    for (int i = 0; i < 16; i++) {
        int idx = tid + i * 256;
        int row = idx >> 5, cc = idx & 31;
        uint32_t dst = smb + (cc >> 2) * 8192 + row * 64 +
                       (uint32_t)(((cc & 3) ^ ((row >> 1) & 3)) << 4);
        CP16(dst, qb + (size_t)row * 256 + cc * 8);
    }
    CP_COMMIT();

    const int lr = lane & 15, lh = lane >> 4;
    const uint32_t qrow = (uint32_t)(wid * 16 + lr);
    const uint32_t qoff = qrow * 64;
    const uint32_t qswz = (qrow >> 1) & 3;
    const uint32_t krA = (uint32_t)lr * 64;
    const uint32_t krB = (uint32_t)(16 + lr) * 64;
    const uint32_t kswz = ((uint32_t)lr >> 1) & 3;

    asm volatile("cp.async.wait_group 0;" ::: "memory");
    __syncthreads();
    uint32_t qreg[16][4];
#pragma unroll
    for (int ks = 0; ks < 16; ks++)
        LDSM4(qreg[ks][0], qreg[ks][1], qreg[ks][2], qreg[ks][3],
              smb + (ks >> 1) * 8192 + qoff +
              (((uint32_t)((ks & 1) * 2 + lh) ^ qswz) << 4));
    __syncthreads();

    auto stage = [&](int c) {
        uint32_t sb = smb + (uint32_t)(c % 6) * 32768;
        const __half* ks_ = kb + (size_t)c * 32 * 256;
        const __half* vs_ = vb + (size_t)c * 32 * 256;
#pragma unroll
        for (int i = 0; i < 4; i++) {
            int idx = tid + i * 256;
            int row = idx >> 5, cc = idx & 31;
            uint32_t off = (cc >> 2) * 2048 + row * 64 +
                           (uint32_t)(((cc & 3) ^ ((row >> 1) & 3)) << 4);
            CP16(sb + off, ks_ + (size_t)row * 256 + cc * 8);
            CP16(sb + 16384 + off, vs_ + (size_t)row * 256 + cc * 8);
        }
        CP_COMMIT();
    };
    stage(0); stage(1); stage(2); stage(3);

    float o[32][4];
#pragma unroll
    for (int nt = 0; nt < 32; nt++)
#pragma unroll
        for (int j = 0; j < 4; j++) o[nt][j] = 0.f;
    float l0 = 0.f, l1 = 0.f;

    auto compute = [&](int c) {
        const uint32_t Ks = smb + (uint32_t)(c % 6) * 32768;
        const uint32_t Vs = Ks + 16384;
        float s[4][4];
#pragma unroll
        for (int j = 0; j < 4; j++)
#pragma unroll
            for (int r = 0; r < 4; r++) s[j][r] = 0.f;
#pragma unroll
        for (int ks = 0; ks < 16; ks++) {
            const uint32_t kc = ((uint32_t)((ks & 1) * 2 + lh) ^ kswz) << 4;
            const uint32_t kp = (ks >> 1) * 2048;
            uint32_t t0, t1, t2, t3;
            LDSM4(t0, t1, t2, t3, Ks + kp + krA + kc);
            mma_f16(s[0], qreg[ks], t0, t2);
            mma_f16(s[1], qreg[ks], t1, t3);
            LDSM4(t0, t1, t2, t3, Ks + kp + krB + kc);
            mma_f16(s[2], qreg[ks], t0, t2);
            mma_f16(s[3], qreg[ks], t1, t3);
        }
        uint32_t pk[2][4];
        __half2 hs0 = __floats2half2_rn(0.f, 0.f);
        __half2 hs1 = hs0;
#pragma unroll
        for (int h = 0; h < 2; h++) {
            pk[h][0] = ex2_h2(pack_h2(s[2 * h][0], s[2 * h][1]));
            pk[h][1] = ex2_h2(pack_h2(s[2 * h][2], s[2 * h][3]));
            pk[h][2] = ex2_h2(pack_h2(s[2 * h + 1][0], s[2 * h + 1][1]));
            pk[h][3] = ex2_h2(pack_h2(s[2 * h + 1][2], s[2 * h + 1][3]));
            hs0 = __hadd2(hs0, __hadd2(*reinterpret_cast<__half2*>(&pk[h][0]),
                                       *reinterpret_cast<__half2*>(&pk[h][2])));
            hs1 = __hadd2(hs1, __hadd2(*reinterpret_cast<__half2*>(&pk[h][1]),
                                       *reinterpret_cast<__half2*>(&pk[h][3])));
        }
        float2 f0 = __half22float2(hs0);
        float2 f1 = __half22float2(hs1);
        l0 += f0.x + f0.y;
        l1 += f1.x + f1.y;
#pragma unroll
        for (int h = 0; h < 2; h++) {
            const uint32_t vr = (h == 0) ? krA : krB;
#pragma unroll
            for (int g2 = 0; g2 < 16; g2++) {
                uint32_t v0, v1, v2, v3;
                LDSM4T(v0, v1, v2, v3,
                       Vs + (g2 >> 1) * 2048 + vr +
                       (((uint32_t)((g2 & 1) * 2 + lh) ^ kswz) << 4));
                mma_f16(o[2 * g2], pk[h], v0, v1);
                mma_f16(o[2 * g2 + 1], pk[h], v2, v3);
            }
        }
    };

    for (int i = 0; i < 64; i++) {
        const int a = 2 * i;
        asm volatile("cp.async.wait_group 2;" ::: "memory");
        __syncthreads();
        if (a + 4 < 128) stage(a + 4); else CP_COMMIT();
        if (a + 5 < 128) stage(a + 5); else CP_COMMIT();
        compute(a);
        compute(a + 1);
    }
    asm volatile("cp.async.wait_group 0;" ::: "memory");

    l0 += __shfl_xor_sync(0xffffffffu, l0, 1);
    l0 += __shfl_xor_sync(0xffffffffu, l0, 2);
    l1 += __shfl_xor_sync(0xffffffffu, l1, 1);
    l1 += __shfl_xor_sync(0xffffffffu, l1, 2);

    const int g = lane >> 2, t2 = (lane & 3) * 2;
    const float i0 = 1.0f / l0, i1 = 1.0f / l1;
    __half* __restrict__ cfb = cfp + b * sQ;
    const int gm0 = row0 + wid * 16 + g;
#pragma unroll
    for (int nt = 0; nt < 32; nt++) {
        const int gn = nt * 8 + t2;
        __half2 h0 = __floats2half2_rn(o[nt][0] * i0, o[nt][1] * i0);
        __half2 h1 = __floats2half2_rn(o[nt][2] * i1, o[nt][3] * i1);
        *reinterpret_cast<__half2*>(&cfb[(size_t)gm0 * CTq + gn]) = h0;
        *reinterpret_cast<__half2*>(&cfb[(size_t)(gm0 + 8) * CTq + gn]) = h1;
    }
}

// ---------------- prep kernels ----------------
__global__ __launch_bounds__(256) void transpose_split(
    const float* __restrict__ x, bf16* __restrict__ xth,
    bf16* __restrict__ xtl, __half* __restrict__ xtf)
{
    __shared__ float t[32][33];
    const int b = blockIdx.z;
    const int n0 = blockIdx.x * 32, c0 = blockIdx.y * 32;
    const int tx = threadIdx.x & 31, ty = threadIdx.x >> 5;
    const float* xb = x + (size_t)b * CCq * NNq;
    bf16* xh = xth + (size_t)b * NNq * CCq;
    bf16* xl = xtl + (size_t)b * NNq * CCq;
    __half* xf = xtf + (size_t)b * NNq * CCq;
#pragma unroll
    for (int p = 0; p < 4; p++)
        t[ty + p * 8][tx] = xb[(size_t)(c0 + ty + p * 8) * NNq + n0 + tx];
    __syncthreads();
#pragma unroll
    for (int p = 0; p < 4; p++) {
        float v = t[tx][ty + p * 8];
        bf16 h = __float2bfloat16(v);
        size_t idx = (size_t)(n0 + ty + p * 8) * CCq + c0 + tx;
        xh[idx] = h;
        xl[idx] = __float2bfloat16(v - __bfloat162float(h));
        xf[idx] = __float2half_rn(v);
    }
}

// merged weight prep: qkv -> fp16 planes; Wo split fp16 / bf16hi/lo
__global__ __launch_bounds__(256) void wprep(
    const float* __restrict__ wq, const float* __restrict__ wk,
    const float* __restrict__ wv, const float* __restrict__ wo,
    __half* __restrict__ fq, __half* __restrict__ fk, __half* __restrict__ fv,
    __half* __restrict__ fo, bf16* __restrict__ oh, bf16* __restrict__ ol)
{
    int i = blockIdx.x * 256 + threadIdx.x;
    if (i < CTq * CCq) {
        fq[i] = __float2half_rn(wq[i]);
        fk[i] = __float2half_rn(wk[i]);
        fv[i] = __float2half_rn(wv[i]);
        // Wo has 2x elements: handle both halves for this index pair
        int o = i >> 8, k = i & 255;       // i over 256x256
        float v0 = wo[(size_t)o * 512 + k];
        float v1 = wo[(size_t)o * 512 + 256 + k];
        fo[o * 256 + k] = __float2half_rn(v0);
        bf16 hh = __float2bfloat16(v1);
        oh[o * 256 + k] = hh;
        ol[o * 256 + k] = __float2bfloat16(v1 - __bfloat162float(hh));
    }
}

// ---------------- launch ----------------
extern "C" void kernel_launch(void* const* d_in, const int* in_sizes, int n_in,
                              void* d_out, int out_size)
{
    const float* x  = (const float*)d_in[0];
    const float* Wq = (const float*)d_in[1];
    const float* Wk = (const float*)d_in[2];
    const float* Wv = (const float*)d_in[3];
    const float* Wo = (const float*)d_in[4];
    float* out = (float*)d_out;

    void *xth, *xtl, *xtf, *qf, *kf, *vf, *cf;
    void *wqf, *wkf, *wvf, *wof, *woh, *wol;
    cudaGetSymbolAddress(&xth, g_xth); cudaGetSymbolAddress(&xtl, g_xtl);
    cudaGetSymbolAddress(&xtf, g_xtf);
    cudaGetSymbolAddress(&qf, g_qf);   cudaGetSymbolAddress(&kf, g_kf);
    cudaGetSymbolAddress(&vf, g_vf);   cudaGetSymbolAddress(&cf, g_cf);
    cudaGetSymbolAddress(&wqf, g_wqf); cudaGetSymbolAddress(&wkf, g_wkf);
    cudaGetSymbolAddress(&wvf, g_wvf); cudaGetSymbolAddress(&wof, g_wof);
    cudaGetSymbolAddress(&woh, g_woh); cudaGetSymbolAddress(&wol, g_wol);

    cudaFuncSetAttribute(qkv_fused, cudaFuncAttributeMaxDynamicSharedMemorySize, QSMEM);
    cudaFuncSetAttribute(gemm_out, cudaFuncAttributeMaxDynamicSharedMemorySize, OSMEM);
    cudaFuncSetAttribute(fmha, cudaFuncAttributeMaxDynamicSharedMemorySize, FM_SMEM);

    dim3 blk(256);

    transpose_split<<<dim3(NNq / 32, CCq / 32, BBq), blk>>>(
        x, (bf16*)xth, (bf16*)xtl, (__half*)xtf);
    wprep<<<dim3(CTq * CCq / 256), blk>>>(
        Wq, Wk, Wv, Wo, (__half*)wqf, (__half*)wkf, (__half*)wvf,
        (__half*)wof, (bf16*)woh, (bf16*)wol);

    qkv_fused<<<dim3(32, 2, BBq), blk, QSMEM>>>(
        (const __half*)xtf, (const __half*)wqf, (const __half*)wkf,
        (const __half*)wvf, (__half*)qf, (__half*)kf, (__half*)vf);

    fmha<<<dim3(32, 1, BBq), blk, FM_SMEM>>>(
        (const __half*)qf, (const __half*)kf, (const __half*)vf, (__half*)cf);

    gemm_out<<<dim3(32, 2, BBq), blk, OSMEM>>>(
        (const __half*)cf, (const bf16*)xth, (const bf16*)xtl,
        (const __half*)wof, (const bf16*)woh, (const bf16*)wol, out);
}

// round 14
// speedup vs baseline: 1.0415x; 1.0415x over previous
#include <cuda_runtime.h>
#include <cuda_bf16.h>
#include <cuda_fp16.h>
#include <cstdint>

#define BBq 4
#define CCq 256
#define NNq 4096
#define CTq 256

typedef __nv_bfloat16 bf16;
typedef __nv_bfloat162 bf162;

// ---------------- persistent planes (device globals) ----------------
__device__ __align__(256) bf16   g_xth[(size_t)BBq * NNq * CCq];
__device__ __align__(256) bf16   g_xtl[(size_t)BBq * NNq * CCq];
__device__ __align__(256) __half g_xtf[(size_t)BBq * NNq * CCq];
__device__ __align__(256) __half g_qf [(size_t)BBq * NNq * CTq];
__device__ __align__(256) __half g_kf [(size_t)BBq * NNq * CTq];
__device__ __align__(256) __half g_vf [(size_t)BBq * NNq * CTq];
__device__ __align__(256) __half g_cf [(size_t)BBq * NNq * CTq];
__device__ __align__(256) __half g_wqf[CTq * CCq];
__device__ __align__(256) __half g_wkf[CTq * CCq];
__device__ __align__(256) __half g_wvf[CTq * CCq];
__device__ __align__(256) __half g_wof[CCq * CTq];      // Wo cols [0,256) fp16
__device__ __align__(256) bf16   g_woh[CCq * CTq];      // Wo cols [256,512) hi
__device__ __align__(256) bf16   g_wol[CCq * CTq];      // Wo cols [256,512) lo

// ---------------- helpers ----------------
__device__ __forceinline__ uint32_t smem_u32(const void* p) {
    uint32_t a;
    asm("{ .reg .u64 t; cvta.to.shared.u64 t, %1; cvt.u32.u64 %0, t; }"
        : "=r"(a) : "l"(p));
    return a;
}
#define CP16(dst, src) \
    asm volatile("cp.async.cg.shared.global [%0], [%1], 16;" \
                 :: "r"(dst), "l"(src))
#define CP_COMMIT() asm volatile("cp.async.commit_group;" ::: "memory")

#define LDSM4(r0, r1, r2, r3, addr) \
    asm volatile("ldmatrix.sync.aligned.m8n8.x4.shared.b16 {%0,%1,%2,%3}, [%4];" \
                 : "=r"(r0), "=r"(r1), "=r"(r2), "=r"(r3) : "r"(addr))
#define LDSM4T(r0, r1, r2, r3, addr) \
    asm volatile("ldmatrix.sync.aligned.m8n8.x4.trans.shared.b16 {%0,%1,%2,%3}, [%4];" \
                 : "=r"(r0), "=r"(r1), "=r"(r2), "=r"(r3) : "r"(addr))

__device__ __forceinline__ void mma_bf16(float* d, const uint32_t* a,
                                         const uint32_t* b) {
    asm volatile(
        "mma.sync.aligned.m16n8k16.row.col.f32.bf16.bf16.f32 "
        "{%0,%1,%2,%3}, {%4,%5,%6,%7}, {%8,%9}, {%0,%1,%2,%3};"
        : "+f"(d[0]), "+f"(d[1]), "+f"(d[2]), "+f"(d[3])
        : "r"(a[0]), "r"(a[1]), "r"(a[2]), "r"(a[3]), "r"(b[0]), "r"(b[1]));
}
__device__ __forceinline__ void mma_f16(float* d, const uint32_t* a,
                                        uint32_t b0, uint32_t b1) {
    asm volatile(
        "mma.sync.aligned.m16n8k16.row.col.f32.f16.f16.f32 "
        "{%0,%1,%2,%3}, {%4,%5,%6,%7}, {%8,%9}, {%0,%1,%2,%3};"
        : "+f"(d[0]), "+f"(d[1]), "+f"(d[2]), "+f"(d[3])
        : "r"(a[0]), "r"(a[1]), "r"(a[2]), "r"(a[3]), "r"(b0), "r"(b1));
}
// f16-accumulator variant: D,C = 2 regs (4 halves) — 2x throughput path
__device__ __forceinline__ void mma_f16h(uint32_t* d, const uint32_t* a,
                                         uint32_t b0, uint32_t b1) {
    asm volatile(
        "mma.sync.aligned.m16n8k16.row.col.f16.f16.f16.f16 "
        "{%0,%1}, {%2,%3,%4,%5}, {%6,%7}, {%0,%1};"
        : "+r"(d[0]), "+r"(d[1])
        : "r"(a[0]), "r"(a[1]), "r"(a[2]), "r"(a[3]), "r"(b0), "r"(b1));
}
__device__ __forceinline__ uint32_t ex2_h2(uint32_t x) {
    uint32_t r;
    asm("ex2.approx.f16x2 %0, %1;" : "=r"(r) : "r"(x));
    return r;
}

// ---------------- fused qkv: single-term fp16 GEMM (R12 validated) --------
#define QSTG 16384
#define QSMEM (4 * QSTG)

__global__ __launch_bounds__(256, 1) void qkv_f16(
    const __half* __restrict__ xtf,
    const __half* __restrict__ Wq, const __half* __restrict__ Wk,
    const __half* __restrict__ Wv,
    __half* __restrict__ qf, __half* __restrict__ kf, __half* __restrict__ vf)
{
    extern __shared__ char sm[];
    const uint32_t smb = smem_u32(sm);
    const int tid = threadIdx.x;
    const int wid = tid >> 5, lane = tid & 31;
    const int w = blockIdx.z % 3, b = blockIdx.z / 3;
    const int row0 = blockIdx.x * 128;
    const int col0 = blockIdx.y * 128;

    const __half* __restrict__ W = (w == 0) ? Wq : (w == 1) ? Wk : Wv;
    __half* __restrict__ D = (w == 0) ? qf : (w == 1) ? kf : vf;
    const float scale = (w == 0) ? 0.0625f * 1.44269504089f : 1.0f;

    const __half* __restrict__ Ab =
        xtf + (long long)b * NNq * CCq + (long long)row0 * CCq;
    const __half* __restrict__ Bb = W + (long long)col0 * CCq;

    int sr[2], sc[2];
    uint32_t sdst[2];
#pragma unroll
    for (int i = 0; i < 2; i++) {
        int idx = tid + i * 256;
        sr[i] = idx >> 2;
        sc[i] = idx & 3;
        sdst[i] = sr[i] * 64 + ((sc[i] ^ ((sr[i] >> 1) & 3)) << 4);
    }
    const int lr = lane & 15, lh = lane >> 4;
    uint32_t aoff[4][2], boff[2][2];
#pragma unroll
    for (int mf = 0; mf < 4; mf++)
#pragma unroll
        for (int ks = 0; ks < 2; ks++) {
            int R = (wid & 1) * 64 + mf * 16 + lr;
            int ch = ks * 2 + lh;
            aoff[mf][ks] = R * 64 + ((ch ^ ((R >> 1) & 3)) << 4);
        }
#pragma unroll
    for (int p = 0; p < 2; p++)
#pragma unroll
        for (int ks = 0; ks < 2; ks++) {
            int R = (wid >> 1) * 32 + p * 16 + lr;
            int ch = ks * 2 + lh;
            boff[p][ks] = R * 64 + ((ch ^ ((R >> 1) & 3)) << 4);
        }

    float acc[4][4][4];
#pragma unroll
    for (int mf = 0; mf < 4; mf++)
#pragma unroll
        for (int nf = 0; nf < 4; nf++)
#pragma unroll
            for (int r = 0; r < 4; r++) acc[mf][nf][r] = 0.f;

    auto stage = [&](int c) {
        const int kc = c * 32;
        const uint32_t sb = smb + (uint32_t)(c & 3) * QSTG;
#pragma unroll
        for (int i = 0; i < 2; i++) {
            CP16(sb + sdst[i],        Ab + (size_t)sr[i] * CCq + kc + sc[i] * 8);
            CP16(sb + 8192 + sdst[i], Bb + (size_t)sr[i] * CCq + kc + sc[i] * 8);
        }
        CP_COMMIT();
    };
    stage(0); stage(1); stage(2);

    for (int c = 0; c < 8; c++) {
        asm volatile("cp.async.wait_group 2;" ::: "memory");
        __syncthreads();
        const uint32_t sb = smb + (uint32_t)(c & 3) * QSTG;
#pragma unroll
        for (int ks = 0; ks < 2; ks++) {
            uint32_t ah[4][4], bh[4][2];
#pragma unroll
            for (int mf = 0; mf < 4; mf++)
                LDSM4(ah[mf][0], ah[mf][1], ah[mf][2], ah[mf][3], sb + aoff[mf][ks]);
#pragma unroll
            for (int p = 0; p < 2; p++) {
                uint32_t t0, t1, t2, t3;
                LDSM4(t0, t1, t2, t3, sb + 8192 + boff[p][ks]);
                bh[2 * p][0] = t0; bh[2 * p][1] = t2;
                bh[2 * p + 1][0] = t1; bh[2 * p + 1][1] = t3;
            }
#pragma unroll
            for (int mf = 0; mf < 4; mf++)
#pragma unroll
                for (int nf = 0; nf < 4; nf++)
                    mma_f16(acc[mf][nf], ah[mf], bh[nf][0], bh[nf][1]);
        }
        if (c + 3 < 8) stage(c + 3);
        else CP_COMMIT();
    }

    const int g = lane >> 2, t2 = (lane & 3) * 2;
    __half* __restrict__ Db = D + (long long)b * NNq * CTq;
#pragma unroll
    for (int mf = 0; mf < 4; mf++) {
        const int gm = row0 + (wid & 1) * 64 + mf * 16 + g;
#pragma unroll
        for (int nf = 0; nf < 4; nf++) {
            const int gn = col0 + (wid >> 1) * 32 + nf * 8 + t2;
            __half2 a01 = __floats2half2_rn(acc[mf][nf][0] * scale,
                                            acc[mf][nf][1] * scale);
            __half2 a23 = __floats2half2_rn(acc[mf][nf][2] * scale,
                                            acc[mf][nf][3] * scale);
            *reinterpret_cast<__half2*>(&Db[(size_t)gm * CTq + gn]) = a01;
            *reinterpret_cast<__half2*>(&Db[(size_t)(gm + 8) * CTq + gn]) = a23;
        }
    }
}

// ---------------- out projection: split precision (unchanged) -------------
#define OSTG 32768
#define OSMEM (4 * OSTG)

__global__ __launch_bounds__(256, 1) void gemm_out(
    const __half* __restrict__ cf,
    const bf16* __restrict__ xth, const bf16* __restrict__ xtl,
    const __half* __restrict__ wof,
    const bf16* __restrict__ woh, const bf16* __restrict__ wol,
    float* __restrict__ Df)
{
    extern __shared__ char sm[];
    const uint32_t smb = smem_u32(sm);
    const int tid = threadIdx.x;
    const int wid = tid >> 5, lane = tid & 31;
    const int row0 = blockIdx.x * 128;
    const int col0 = blockIdx.y * 128;
    const int b = blockIdx.z;

    const __half* __restrict__ Afb = cf + (long long)b * NNq * CTq +
                                     (long long)row0 * CTq;
    const bf16* __restrict__ Ahb = xth + (long long)b * NNq * CCq +
                                   (long long)row0 * CCq;
    const bf16* __restrict__ Alb = xtl + (long long)b * NNq * CCq +
                                   (long long)row0 * CCq;
    const __half* __restrict__ Bfb = wof + (size_t)col0 * CTq;
    const bf16* __restrict__ Bhb = woh + (size_t)col0 * CTq;
    const bf16* __restrict__ Blb = wol + (size_t)col0 * CTq;

    int sr[2], sc[2];
    uint32_t sdst[2];
#pragma unroll
    for (int i = 0; i < 2; i++) {
        int idx = tid + i * 256;
        sr[i] = idx >> 2;
        sc[i] = idx & 3;
        sdst[i] = sr[i] * 64 + ((sc[i] ^ ((sr[i] >> 1) & 3)) << 4);
    }
    const int lr = lane & 15, lh = lane >> 4;
    uint32_t aoff[4][2], boff[2][2];
#pragma unroll
    for (int mf = 0; mf < 4; mf++)
#pragma unroll
        for (int ks = 0; ks < 2; ks++) {
            int R = (wid & 1) * 64 + mf * 16 + lr;
            int ch = ks * 2 + lh;
            aoff[mf][ks] = R * 64 + ((ch ^ ((R >> 1) & 3)) << 4);
        }
#pragma unroll
    for (int p = 0; p < 2; p++)
#pragma unroll
        for (int ks = 0; ks < 2; ks++) {
            int R = (wid >> 1) * 32 + p * 16 + lr;
            int ch = ks * 2 + lh;
            boff[p][ks] = R * 64 + ((ch ^ ((R >> 1) & 3)) << 4);
        }

    float acc[4][4][4];
#pragma unroll
    for (int mf = 0; mf < 4; mf++)
#pragma unroll
        for (int nf = 0; nf < 4; nf++)
#pragma unroll
            for (int r = 0; r < 4; r++) acc[mf][nf][r] = 0.f;

    auto stageg = [&](int gc) {
        const uint32_t sb = smb + (uint32_t)(gc & 3) * OSTG;
        if (gc < 8) {
            const int kc = gc * 32;
#pragma unroll
            for (int i = 0; i < 2; i++) {
                CP16(sb + sdst[i],        Afb + (size_t)sr[i] * CTq + kc + sc[i] * 8);
                CP16(sb + 8192 + sdst[i], Bfb + (size_t)sr[i] * CTq + kc + sc[i] * 8);
            }
        } else {
            const int kc = (gc - 8) * 32;
#pragma unroll
            for (int i = 0; i < 2; i++) {
                const uint32_t d = sdst[i];
                CP16(sb + d,         Ahb + (size_t)sr[i] * CCq + kc + sc[i] * 8);
                CP16(sb + 8192 + d,  Alb + (size_t)sr[i] * CCq + kc + sc[i] * 8);
                CP16(sb + 16384 + d, Bhb + (size_t)sr[i] * CTq + kc + sc[i] * 8);
                CP16(sb + 24576 + d, Blb + (size_t)sr[i] * CTq + kc + sc[i] * 8);
            }
        }
        CP_COMMIT();
    };

    stageg(0); stageg(1); stageg(2);

    for (int gc = 0; gc < 16; gc++) {
        asm volatile("cp.async.wait_group 2;" ::: "memory");
        __syncthreads();
        const uint32_t sb = smb + (uint32_t)(gc & 3) * OSTG;
        if (gc < 8) {
#pragma unroll
            for (int ks = 0; ks < 2; ks++) {
                uint32_t ah[4][4], bh[4][2];
#pragma unroll
                for (int mf = 0; mf < 4; mf++)
                    LDSM4(ah[mf][0], ah[mf][1], ah[mf][2], ah[mf][3],
                          sb + aoff[mf][ks]);
#pragma unroll
                for (int p = 0; p < 2; p++) {
                    uint32_t t0, t1, t2, t3;
                    LDSM4(t0, t1, t2, t3, sb + 8192 + boff[p][ks]);
                    bh[2 * p][0] = t0; bh[2 * p][1] = t2;
                    bh[2 * p + 1][0] = t1; bh[2 * p + 1][1] = t3;
                }
#pragma unroll
                for (int mf = 0; mf < 4; mf++)
#pragma unroll
                    for (int nf = 0; nf < 4; nf++)
                        mma_f16(acc[mf][nf], ah[mf], bh[nf][0], bh[nf][1]);
            }
        } else {
#pragma unroll
            for (int ks = 0; ks < 2; ks++) {
                uint32_t ah[4][4], al[4][4], bh[4][2], bl[4][2];
#pragma unroll
                for (int mf = 0; mf < 4; mf++) {
                    LDSM4(ah[mf][0], ah[mf][1], ah[mf][2], ah[mf][3],
                          sb + aoff[mf][ks]);
                    LDSM4(al[mf][0], al[mf][1], al[mf][2], al[mf][3],
                          sb + 8192 + aoff[mf][ks]);
                }
#pragma unroll
                for (int p = 0; p < 2; p++) {
                    uint32_t t0, t1, t2, t3;
                    LDSM4(t0, t1, t2, t3, sb + 16384 + boff[p][ks]);
                    bh[2 * p][0] = t0; bh[2 * p][1] = t2;
                    bh[2 * p + 1][0] = t1; bh[2 * p + 1][1] = t3;
                    LDSM4(t0, t1, t2, t3, sb + 24576 + boff[p][ks]);
                    bl[2 * p][0] = t0; bl[2 * p][1] = t2;
                    bl[2 * p + 1][0] = t1; bl[2 * p + 1][1] = t3;
                }
#pragma unroll
                for (int mf = 0; mf < 4; mf++)
#pragma unroll
                    for (int nf = 0; nf < 4; nf++) {
                        mma_bf16(acc[mf][nf], ah[mf], bh[nf]);
                        mma_bf16(acc[mf][nf], ah[mf], bl[nf]);
                        mma_bf16(acc[mf][nf], al[mf], bh[nf]);
                    }
            }
        }
        if (gc + 3 < 16) stageg(gc + 3);
        else CP_COMMIT();
    }

    const int g = lane >> 2, t2 = (lane & 3) * 2;
    float* __restrict__ Dfb = Df + (long long)b * CCq * NNq;
#pragma unroll
    for (int mf = 0; mf < 4; mf++) {
        const int gm = row0 + (wid & 1) * 64 + mf * 16 + g;
#pragma unroll
        for (int nf = 0; nf < 4; nf++) {
            const int gn = col0 + (wid >> 1) * 32 + nf * 8 + t2;
            Dfb[(size_t)gn * NNq + gm] = acc[mf][nf][0];
            Dfb[(size_t)(gn + 1) * NNq + gm] = acc[mf][nf][1];
            Dfb[(size_t)gn * NNq + gm + 8] = acc[mf][nf][2];
            Dfb[(size_t)(gn + 1) * NNq + gm + 8] = acc[mf][nf][3];
        }
    }
}

// ---------------- fused attention: fp16-accum MMA core ----------
#define FM_SMEM 196608

__global__ __launch_bounds__(256, 1) void fmha(
    const __half* __restrict__ qf, const __half* __restrict__ kf,
    const __half* __restrict__ vf, __half* __restrict__ cfp)
{
    extern __shared__ char sm[];
    const uint32_t smb = smem_u32(sm);
    const int tid = threadIdx.x, wid = tid >> 5, lane = tid & 31;
    const int b = blockIdx.z, row0 = blockIdx.x * 128;
    const long long sQ = (long long)NNq * CTq;
    const __half* __restrict__ qb = qf + b * sQ + (long long)row0 * CTq;
    const __half* __restrict__ kb = kf + b * sQ;
    const __half* __restrict__ vb = vf + b * sQ;

    // ---- stage Q into [0, 64KB) (freed after register hoist) ----
#pragma unroll
    for (int i = 0; i < 16; i++) {
        int idx = tid + i * 256;
        int row = idx >> 5, cc = idx & 31;
        uint32_t dst = smb + (cc >> 2) * 8192 + row * 64 +
                       (uint32_t)(((cc & 3) ^ ((row >> 1) & 3)) << 4);
        CP16(dst, qb + (size_t)row * 256 + cc * 8);
    }
    CP_COMMIT();

    const int lr = lane & 15, lh = lane >> 4;
    const uint32_t qrow = (uint32_t)(wid * 16 + lr);
    const uint32_t qoff = qrow * 64;
    const uint32_t qswz = (qrow >> 1) & 3;
    const uint32_t krA = (uint32_t)lr * 64;
    const uint32_t krB = (uint32_t)(16 + lr) * 64;
    const uint32_t kswz = ((uint32_t)lr >> 1) & 3;

    asm volatile("cp.async.wait_group 0;" ::: "memory");
    __syncthreads();
    uint32_t qreg[16][4];
#pragma unroll
    for (int ks = 0; ks < 16; ks++)
        LDSM4(qreg[ks][0], qreg[ks][1], qreg[ks][2], qreg[ks][3],
              smb + (ks >> 1) * 8192 + qoff +
              (((uint32_t)((ks & 1) * 2 + lh) ^ qswz) << 4));
    __syncthreads();

    auto stage = [&](int c) {
        uint32_t sb = smb + (uint32_t)(c % 6) * 32768;
        const __half* ks_ = kb + (size_t)c * 32 * 256;
        const __half* vs_ = vb + (size_t)c * 32 * 256;
#pragma unroll
        for (int i = 0; i < 4; i++) {
            int idx = tid + i * 256;
            int row = idx >> 5, cc = idx & 31;
            uint32_t off = (cc >> 2) * 2048 + row * 64 +
                           (uint32_t)(((cc & 3) ^ ((row >> 1) & 3)) << 4);
            CP16(sb + off, ks_ + (size_t)row * 256 + cc * 8);
            CP16(sb + 16384 + off, vs_ + (size_t)row * 256 + cc * 8);
        }
        CP_COMMIT();
    };
    stage(0); stage(1); stage(2); stage(3);

    // O accumulators in fp16 (packed half2): o[nt][0] rows g, o[nt][1] rows g+8
    uint32_t o[32][2];
#pragma unroll
    for (int nt = 0; nt < 32; nt++) { o[nt][0] = 0u; o[nt][1] = 0u; }
    float l0 = 0.f, l1 = 0.f;

    auto compute = [&](int c) {
        const uint32_t Ks = smb + (uint32_t)(c % 6) * 32768;
        const uint32_t Vs = Ks + 16384;
        // S accumulators in fp16: sac[j][0]={c0,c1} rows g, sac[j][1] rows g+8
        uint32_t sac[4][2];
#pragma unroll
        for (int j = 0; j < 4; j++) { sac[j][0] = 0u; sac[j][1] = 0u; }
#pragma unroll
        for (int ks = 0; ks < 16; ks++) {
            const uint32_t kc = ((uint32_t)((ks & 1) * 2 + lh) ^ kswz) << 4;
            const uint32_t kp = (ks >> 1) * 2048;
            uint32_t t0, t1, t2, t3;
            LDSM4(t0, t1, t2, t3, Ks + kp + krA + kc);
            mma_f16h(sac[0], qreg[ks], t0, t2);
            mma_f16h(sac[1], qreg[ks], t1, t3);
            LDSM4(t0, t1, t2, t3, Ks + kp + krB + kc);
            mma_f16h(sac[2], qreg[ks], t0, t2);
            mma_f16h(sac[3], qreg[ks], t1, t3);
        }

        // P = 2^S directly on fp16 C fragments; row sums in fp16 -> fp32
        uint32_t pk[2][4];
        __half2 hs0 = __floats2half2_rn(0.f, 0.f);
        __half2 hs1 = hs0;
#pragma unroll
        for (int h = 0; h < 2; h++) {
            pk[h][0] = ex2_h2(sac[2 * h][0]);
            pk[h][1] = ex2_h2(sac[2 * h][1]);
            pk[h][2] = ex2_h2(sac[2 * h + 1][0]);
            pk[h][3] = ex2_h2(sac[2 * h + 1][1]);
            hs0 = __hadd2(hs0, __hadd2(*reinterpret_cast<__half2*>(&pk[h][0]),
                                       *reinterpret_cast<__half2*>(&pk[h][2])));
            hs1 = __hadd2(hs1, __hadd2(*reinterpret_cast<__half2*>(&pk[h][1]),
                                       *reinterpret_cast<__half2*>(&pk[h][3])));
        }
        float2 f0 = __half22float2(hs0);
        float2 f1 = __half22float2(hs1);
        l0 += f0.x + f0.y;
        l1 += f1.x + f1.y;

        // O += P V  (fp16 accumulate)
#pragma unroll
        for (int h = 0; h < 2; h++) {
            const uint32_t vr = (h == 0) ? krA : krB;
#pragma unroll
            for (int g2 = 0; g2 < 16; g2++) {
                uint32_t v0, v1, v2, v3;
                LDSM4T(v0, v1, v2, v3,
                       Vs + (g2 >> 1) * 2048 + vr +
                       (((uint32_t)((g2 & 1) * 2 + lh) ^ kswz) << 4));
                mma_f16h(o[2 * g2], pk[h], v0, v1);
                mma_f16h(o[2 * g2 + 1], pk[h], v2, v3);
            }
        }
    };

    for (int i = 0; i < 64; i++) {
        const int a = 2 * i;
        asm volatile("cp.async.wait_group 2;" ::: "memory");
        __syncthreads();
        if (a + 4 < 128) stage(a + 4); else CP_COMMIT();
        if (a + 5 < 128) stage(a + 5); else CP_COMMIT();
        compute(a);
        compute(a + 1);
    }
    asm volatile("cp.async.wait_group 0;" ::: "memory");

    l0 += __shfl_xor_sync(0xffffffffu, l0, 1);
    l0 += __shfl_xor_sync(0xffffffffu, l0, 2);
    l1 += __shfl_xor_sync(0xffffffffu, l1, 1);
    l1 += __shfl_xor_sync(0xffffffffu, l1, 2);

    const int g = lane >> 2, t2 = (lane & 3) * 2;
    const float i0 = 1.0f / l0, i1 = 1.0f / l1;
    __half* __restrict__ cfb = cfp + b * sQ;
    const int gm0 = row0 + wid * 16 + g;
#pragma unroll
    for (int nt = 0; nt < 32; nt++) {
        const int gn = nt * 8 + t2;
        float2 a0 = __half22float2(*reinterpret_cast<__half2*>(&o[nt][0]));
        float2 a1 = __half22float2(*reinterpret_cast<__half2*>(&o[nt][1]));
        __half2 h0 = __floats2half2_rn(a0.x * i0, a0.y * i0);
        __half2 h1 = __floats2half2_rn(a1.x * i1, a1.y * i1);
        *reinterpret_cast<__half2*>(&cfb[(size_t)gm0 * CTq + gn]) = h0;
        *reinterpret_cast<__half2*>(&cfb[(size_t)(gm0 + 8) * CTq + gn]) = h1;
    }
}

// ---------------- prep kernels ----------------
__global__ __launch_bounds__(256) void transpose_split(
    const float* __restrict__ x, bf16* __restrict__ xth,
    bf16* __restrict__ xtl, __half* __restrict__ xtf)
{
    __shared__ float t[32][33];
    const int b = blockIdx.z;
    const int n0 = blockIdx.x * 32, c0 = blockIdx.y * 32;
    const int tx = threadIdx.x & 31, ty = threadIdx.x >> 5;
    const float* xb = x + (size_t)b * CCq * NNq;
    bf16* xh = xth + (size_t)b * NNq * CCq;
    bf16* xl = xtl + (size_t)b * NNq * CCq;
    __half* xf = xtf + (size_t)b * NNq * CCq;
#pragma unroll
    for (int p = 0; p < 4; p++)
        t[ty + p * 8][tx] = xb[(size_t)(c0 + ty + p * 8) * NNq + n0 + tx];
    __syncthreads();
#pragma unroll
    for (int p = 0; p < 4; p++) {
        float v = t[tx][ty + p * 8];
        bf16 h = __float2bfloat16(v);
        size_t idx = (size_t)(n0 + ty + p * 8) * CCq + c0 + tx;
        xh[idx] = h;
        xl[idx] = __float2bfloat16(v - __bfloat162float(h));
        xf[idx] = __float2half_rn(v);
    }
}

// merged weight prep: qkv -> fp16 planes; Wo split fp16 / bf16hi/lo
__global__ __launch_bounds__(256) void wprep(
    const float* __restrict__ wq, const float* __restrict__ wk,
    const float* __restrict__ wv, const float* __restrict__ wo,
    __half* __restrict__ fq, __half* __restrict__ fk, __half* __restrict__ fv,
    __half* __restrict__ fo, bf16* __restrict__ oh, bf16* __restrict__ ol)
{
    int i = blockIdx.x * 256 + threadIdx.x;
    if (i < CTq * CCq) {
        fq[i] = __float2half_rn(wq[i]);
        fk[i] = __float2half_rn(wk[i]);
        fv[i] = __float2half_rn(wv[i]);
        int o = i >> 8, k = i & 255;
        float v0 = wo[(size_t)o * 512 + k];
        float v1 = wo[(size_t)o * 512 + 256 + k];
        fo[o * 256 + k] = __float2half_rn(v0);
        bf16 hh = __float2bfloat16(v1);
        oh[o * 256 + k] = hh;
        ol[o * 256 + k] = __float2bfloat16(v1 - __bfloat162float(hh));
    }
}

// ---------------- launch ----------------
extern "C" void kernel_launch(void* const* d_in, const int* in_sizes, int n_in,
                              void* d_out, int out_size)
{
    const float* x  = (const float*)d_in[0];
    const float* Wq = (const float*)d_in[1];
    const float* Wk = (const float*)d_in[2];
    const float* Wv = (const float*)d_in[3];
    const float* Wo = (const float*)d_in[4];
    float* out = (float*)d_out;

    void *xth, *xtl, *xtf, *qf, *kf, *vf, *cf;
    void *wqf, *wkf, *wvf, *wof, *woh, *wol;
    cudaGetSymbolAddress(&xth, g_xth); cudaGetSymbolAddress(&xtl, g_xtl);
    cudaGetSymbolAddress(&xtf, g_xtf);
    cudaGetSymbolAddress(&qf, g_qf);   cudaGetSymbolAddress(&kf, g_kf);
    cudaGetSymbolAddress(&vf, g_vf);   cudaGetSymbolAddress(&cf, g_cf);
    cudaGetSymbolAddress(&wqf, g_wqf); cudaGetSymbolAddress(&wkf, g_wkf);
    cudaGetSymbolAddress(&wvf, g_wvf); cudaGetSymbolAddress(&wof, g_wof);
    cudaGetSymbolAddress(&woh, g_woh); cudaGetSymbolAddress(&wol, g_wol);

    cudaFuncSetAttribute(qkv_f16, cudaFuncAttributeMaxDynamicSharedMemorySize, QSMEM);
    cudaFuncSetAttribute(gemm_out, cudaFuncAttributeMaxDynamicSharedMemorySize, OSMEM);
    cudaFuncSetAttribute(fmha, cudaFuncAttributeMaxDynamicSharedMemorySize, FM_SMEM);

    dim3 blk(256);

    transpose_split<<<dim3(NNq / 32, CCq / 32, BBq), blk>>>(
        x, (bf16*)xth, (bf16*)xtl, (__half*)xtf);
    wprep<<<dim3(CTq * CCq / 256), blk>>>(
        Wq, Wk, Wv, Wo, (__half*)wqf, (__half*)wkf, (__half*)wvf,
        (__half*)wof, (bf16*)woh, (bf16*)wol);

    qkv_f16<<<dim3(32, 2, BBq * 3), blk, QSMEM>>>(
        (const __half*)xtf, (const __half*)wqf, (const __half*)wkf,
        (const __half*)wvf, (__half*)qf, (__half*)kf, (__half*)vf);

    fmha<<<dim3(32, 1, BBq), blk, FM_SMEM>>>(
        (const __half*)qf, (const __half*)kf, (const __half*)vf, (__half*)cf);

    gemm_out<<<dim3(32, 2, BBq), blk, OSMEM>>>(
        (const __half*)cf, (const bf16*)xth, (const bf16*)xtl,
        (const __half*)wof, (const bf16*)woh, (const bf16*)wol, out);
}